// round 14
// baseline (speedup 1.0000x reference)
#include <cuda_runtime.h>
#include <math.h>
#include <stdint.h>

#define N_NODES 4096
#define F_IN    256
#define C_TOT   256
#define HEADS   4
#define F_OUT   64
#define JSPLIT  2
#define NWORDS  (N_NODES / 32)
#define JTILE   64
#define JPER    (N_NODES / JSPLIT)
#define NT      (JPER / JTILE)       // 32 tiles per CTA
#define HSTR    72
#define HS_FLOATS (JTILE * HSTR)     // 4608 floats per buffer
#define AGGR_SMEM (3 * HS_FLOATS * 4 + 3 * JTILE * 8)   // 56832 B

__device__ float    g_h [N_NODES * C_TOT];
__device__ float2   g_Pq[HEADS * N_NODES];   // (exp(e_i), exp(0.2 e_i)) [head][n]
__device__ float2   g_Qq[HEADS * N_NODES];   // (exp(e_j), exp(0.2 e_j)) [head][n]
__device__ unsigned g_adjm[N_NODES * NWORDS];
__device__ float    g_part[JSPLIT * HEADS * N_NODES * F_OUT];
__device__ float    g_pden[JSPLIT * HEADS * N_NODES];

// ---------------- cp.async helpers ----------------
__device__ __forceinline__ void cp16(uint32_t dst, const void* src) {
    asm volatile("cp.async.cg.shared.global [%0], [%1], 16;" :: "r"(dst), "l"(src));
}
#define CP_COMMIT() asm volatile("cp.async.commit_group;" ::: "memory")
#define CP_WAIT1()  asm volatile("cp.async.wait_group 1;" ::: "memory")
#define CP_WAIT0()  asm volatile("cp.async.wait_group 0;" ::: "memory")

// ---------------------------------------------------------------------------
// K1: fused gemm + exp epilogue (bid < 256) || adj bit-pack (bid >= 256).
//  Pack CTAs stream 64 MB of adj concurrently with compute-bound gemm CTAs.
// ---------------------------------------------------------------------------
__global__ __launch_bounds__(256) void k_gemm_pack(const float* __restrict__ x,
                                                   const float* __restrict__ W,
                                                   const float* __restrict__ aa,
                                                   const int* __restrict__ adj) {
    const int bid = blockIdx.x;
    const int t   = threadIdx.x;

    if (bid >= 256) {
        // ---- pack: 32 CTAs x 128 rows ----
        const int pid  = bid - 256;
        const int w    = t >> 5;
        const int lane = t & 31;
#pragma unroll 1
        for (int r = 0; r < 16; ++r) {
            const int row = pid * 128 + w * 16 + r;
            const size_t rb = (size_t)row * N_NODES;
#pragma unroll 1
            for (int c = 0; c < 32; ++c) {
                int4 v = *(const int4*)&adj[rb + c * 128 + lane * 4];
                unsigned n = (v.x != 0 ? 1u : 0u) | (v.y != 0 ? 2u : 0u)
                           | (v.z != 0 ? 4u : 0u) | (v.w != 0 ? 8u : 0u);
                unsigned word = n << (4 * (lane & 7));
                word |= __shfl_xor_sync(0xffffffffu, word, 1);
                word |= __shfl_xor_sync(0xffffffffu, word, 2);
                word |= __shfl_xor_sync(0xffffffffu, word, 4);
                if ((lane & 7) == 0)
                    g_adjm[row * NWORDS + c * 4 + (lane >> 3)] = word;
            }
        }
        return;
    }

    // ---- gemm: proven 64x64 tiling ----
    __shared__ __align__(16) float As[16][64];
    __shared__ __align__(16) float Bs[16][64];
    const int bx = bid & 3;            // head
    const int by = bid >> 2;
    const int n0 = bx * 64;
    const int m0 = by * 64;
    const int tx = t & 15, ty = t >> 4;

    float acc[4][4];
#pragma unroll
    for (int i = 0; i < 4; ++i)
#pragma unroll
        for (int j = 0; j < 4; ++j) acc[i][j] = 0.f;

    for (int k0 = 0; k0 < F_IN; k0 += 16) {
        {
            int row = t >> 2, k4 = (t & 3) * 4;
            float4 v = *(const float4*)&x[(m0 + row) * F_IN + k0 + k4];
            As[k4 + 0][row] = v.x; As[k4 + 1][row] = v.y;
            As[k4 + 2][row] = v.z; As[k4 + 3][row] = v.w;
        }
        {
            int krow = t >> 4, n4 = (t & 15) * 4;
            *(float4*)&Bs[krow][n4] = *(const float4*)&W[(k0 + krow) * C_TOT + n0 + n4];
        }
        __syncthreads();
#pragma unroll
        for (int kk = 0; kk < 16; ++kk) {
            float a[4], b[4];
            *(float4*)a = *(float4*)&As[kk][ty * 4];
            *(float4*)b = *(float4*)&Bs[kk][tx * 4];
#pragma unroll
            for (int i = 0; i < 4; ++i)
#pragma unroll
                for (int j = 0; j < 4; ++j) acc[i][j] += a[i] * b[j];
        }
        __syncthreads();
    }
#pragma unroll
    for (int i = 0; i < 4; ++i) {
        float4 v = make_float4(acc[i][0], acc[i][1], acc[i][2], acc[i][3]);
        *(float4*)&g_h[(size_t)(m0 + ty * 4 + i) * C_TOT + n0 + tx * 4] = v;
    }

    // fused exp-table epilogue
    const int f0 = tx * 4;
    float4 a1v = *(const float4*)&aa[f0];
    float4 a2v = *(const float4*)&aa[64 + f0];
#pragma unroll
    for (int i = 0; i < 4; ++i) {
        float ei = acc[i][0] * a1v.x + acc[i][1] * a1v.y
                 + acc[i][2] * a1v.z + acc[i][3] * a1v.w;
        float ej = acc[i][0] * a2v.x + acc[i][1] * a2v.y
                 + acc[i][2] * a2v.z + acc[i][3] * a2v.w;
#pragma unroll
        for (int off = 8; off; off >>= 1) {
            ei += __shfl_down_sync(0xffffffffu, ei, off, 16);
            ej += __shfl_down_sync(0xffffffffu, ej, off, 16);
        }
        if (tx == 0) {
            int idx = bx * N_NODES + m0 + ty * 4 + i;
            g_Pq[idx] = make_float2(expf(ei), expf(0.2f * ei));
            g_Qq[idx] = make_float2(expf(ej), expf(0.2f * ej));
        }
    }
}

// ---------------------------------------------------------------------------
// K3: tf32 mma.sync aggregation, v7 = v6 inner loop + triple-buffered
//  cp.async (one __syncthreads per tile) + JSPLIT=2 (512 CTAs, 55.8 KB smem
//  -> 4 CTAs/SM -> single wave, no tail).
// ---------------------------------------------------------------------------
__device__ __forceinline__ void mma_tf32(float c[4],
                                         unsigned a0, unsigned a1,
                                         unsigned a2, unsigned a3,
                                         unsigned b0, unsigned b1) {
    asm volatile(
        "mma.sync.aligned.m16n8k8.row.col.f32.tf32.tf32.f32 "
        "{%0,%1,%2,%3}, {%4,%5,%6,%7}, {%8,%9}, {%0,%1,%2,%3};"
        : "+f"(c[0]), "+f"(c[1]), "+f"(c[2]), "+f"(c[3])
        : "r"(a0), "r"(a1), "r"(a2), "r"(a3), "r"(b0), "r"(b1));
}
__device__ __forceinline__ unsigned to_tf32(float x) {
    unsigned u;
    asm("cvt.rna.tf32.f32 %0, %1;" : "=r"(u) : "f"(x));
    return u;
}

__global__ __launch_bounds__(128) void k_aggr_v7() {
    extern __shared__ __align__(16) float dsm[];
    float* hsb[3] = {dsm, dsm + HS_FLOATS, dsm + 2 * HS_FLOATS};
    float2* qsb[3] = {(float2*)(dsm + 3 * HS_FLOATS),
                      (float2*)(dsm + 3 * HS_FLOATS) + JTILE,
                      (float2*)(dsm + 3 * HS_FLOATS) + 2 * JTILE};

    const int t    = threadIdx.x;
    const int w    = t >> 5;
    const int lane = t & 31;
    const int g    = lane >> 2;
    const int tg   = lane & 3;
    const int head = blockIdx.y;
    const int js   = blockIdx.z;
    const int i0   = blockIdx.x * 64;
    const int row0 = i0 + w * 16 + g;
    const int row1 = row0 + 8;

    const float2 pa = g_Pq[head * N_NODES + row0];
    const float2 pb = g_Pq[head * N_NODES + row1];

    float acc[8][4];
#pragma unroll
    for (int nt = 0; nt < 8; ++nt)
#pragma unroll
        for (int k = 0; k < 4; ++k) acc[nt][k] = 0.f;
    float d0 = 0.f, d1 = 0.f;

    const unsigned* am0 = g_adjm + row0 * NWORDS;
    const unsigned* am1 = g_adjm + row1 * NWORDS;

    uint32_t hsa[3], qsa[3];
#pragma unroll
    for (int b = 0; b < 3; ++b) {
        hsa[b] = (uint32_t)__cvta_generic_to_shared(hsb[b]);
        qsa[b] = (uint32_t)__cvta_generic_to_shared(qsb[b]);
    }
    const int jbase = js * JPER;

    // ---- prologue: stage tiles 0,1 ----
#pragma unroll
    for (int pt = 0; pt < 2; ++pt) {
        const int j0 = jbase + pt * JTILE;
#pragma unroll
        for (int s = 0; s < 8; ++s) {
            int c = t + s * 128;
            int jj = c >> 4, cc = c & 15;
            cp16(hsa[pt] + (jj * HSTR + cc * 4) * 4,
                 &g_h[(size_t)(j0 + jj) * C_TOT + head * F_OUT + cc * 4]);
        }
        if (t < 32)
            cp16(qsa[pt] + t * 16, &g_Qq[head * N_NODES + j0 + t * 2]);
        CP_COMMIT();
    }

#pragma unroll 1
    for (int tile = 0; tile < NT; ++tile) {
        const int buf = tile % 3;
        const int j0  = jbase + tile * JTILE;

        if (tile < NT - 1) CP_WAIT1(); else CP_WAIT0();
        __syncthreads();   // all staging of this buf visible; separates prior compute

        const float*  hsp = hsb[buf];
        const float2* qsp = qsb[buf];
        const int wd = j0 >> 5;
        const unsigned m0a = am0[wd], m0b = am0[wd + 1];
        const unsigned m1a = am1[wd], m1b = am1[wd + 1];

#pragma unroll
        for (int kk = 0; kk < 8; ++kk) {
            const unsigned w0 = (kk < 4) ? m0a : m0b;
            const unsigned w1 = (kk < 4) ? m1a : m1b;
            const int sl   = (kk * 8) & 31;
            const int j_lo = kk * 8 + tg;
            const int j_hi = j_lo + 4;
            const float2 qlo = qsp[j_lo];
            const float2 qhi = qsp[j_hi];

            float v00 = fmaxf(pa.x * qlo.x, pa.y * qlo.y);
            float v10 = fmaxf(pb.x * qlo.x, pb.y * qlo.y);
            float v01 = fmaxf(pa.x * qhi.x, pa.y * qhi.y);
            float v11 = fmaxf(pb.x * qhi.x, pb.y * qhi.y);
            float a00 = ((w0 >> (sl + tg))     & 1u) ? v00 : 0.f;
            float a10 = ((w1 >> (sl + tg))     & 1u) ? v10 : 0.f;
            float a01 = ((w0 >> (sl + tg + 4)) & 1u) ? v01 : 0.f;
            float a11 = ((w1 >> (sl + tg + 4)) & 1u) ? v11 : 0.f;

            unsigned ua0 = to_tf32(a00);
            unsigned ua1 = to_tf32(a10);
            unsigned ua2 = to_tf32(a01);
            unsigned ua3 = to_tf32(a11);
            d0 += __uint_as_float(ua0) + __uint_as_float(ua2);
            d1 += __uint_as_float(ua1) + __uint_as_float(ua3);

            const float* blo = &hsp[j_lo * HSTR + g];
            const float* bhi = &hsp[j_hi * HSTR + g];
#pragma unroll
            for (int nt = 0; nt < 8; ++nt) {
                unsigned b0 = __float_as_uint(blo[nt * 8]);
                unsigned b1 = __float_as_uint(bhi[nt * 8]);
                mma_tf32(acc[nt], ua0, ua1, ua2, ua3, b0, b1);
            }
        }

        // ---- stage tile+2 into buf (tile+2)%3 (consumed at tile-1; safe) ----
        if (tile + 2 < NT) {
            const int jn = j0 + 2 * JTILE;
            const int nb = (tile + 2) % 3;
#pragma unroll
            for (int s = 0; s < 8; ++s) {
                int c = t + s * 128;
                int jj = c >> 4, cc = c & 15;
                cp16(hsa[nb] + (jj * HSTR + cc * 4) * 4,
                     &g_h[(size_t)(jn + jj) * C_TOT + head * F_OUT + cc * 4]);
            }
            if (t < 32)
                cp16(qsa[nb] + t * 16, &g_Qq[head * N_NODES + jn + t * 2]);
            CP_COMMIT();
        }
    }

    // ---- epilogue ----
    d0 += __shfl_xor_sync(0xffffffffu, d0, 1);
    d0 += __shfl_xor_sync(0xffffffffu, d0, 2);
    d1 += __shfl_xor_sync(0xffffffffu, d1, 1);
    d1 += __shfl_xor_sync(0xffffffffu, d1, 2);

    const size_t pb2 = (size_t)(js * HEADS + head) * N_NODES;
    if (tg == 0) {
        g_pden[pb2 + row0] = d0;
        g_pden[pb2 + row1] = d1;
    }
    float* p0 = &g_part[(pb2 + row0) * F_OUT];
    float* p1 = &g_part[(pb2 + row1) * F_OUT];
#pragma unroll
    for (int nt = 0; nt < 8; ++nt) {
        const int f = nt * 8 + tg * 2;
        *(float2*)&p0[f] = make_float2(acc[nt][0], acc[nt][1]);
        *(float2*)&p1[f] = make_float2(acc[nt][2], acc[nt][3]);
    }
}

// ---------------------------------------------------------------------------
// K4: combine partials over j-splits and heads
// ---------------------------------------------------------------------------
__global__ __launch_bounds__(256) void k_combine(float* __restrict__ out) {
    const int t = blockIdx.x * 256 + threadIdx.x;
    const int i = t >> 6;
    const int f = t & 63;
    float v = 0.f;
#pragma unroll
    for (int h = 0; h < HEADS; ++h) {
        float num = 0.f, den = 0.f;
#pragma unroll
        for (int s = 0; s < JSPLIT; ++s) {
            num += g_part[((size_t)(s * HEADS + h) * N_NODES + i) * F_OUT + f];
            den += g_pden[(size_t)(s * HEADS + h) * N_NODES + i];
        }
        v += num / den;
    }
    out[t] = 0.25f * v;
}

// ---------------------------------------------------------------------------
extern "C" void kernel_launch(void* const* d_in, const int* in_sizes, int n_in,
                              void* d_out, int out_size) {
    const float* x   = (const float*)d_in[0];
    const int*   adj = (const int*)  d_in[1];
    const float* W   = (const float*)d_in[2];
    const float* a   = (const float*)d_in[3];
    float* out = (float*)d_out;

    static int smem_set = 0;
    if (!smem_set) {
        cudaFuncSetAttribute(k_aggr_v7,
                             cudaFuncAttributeMaxDynamicSharedMemorySize,
                             AGGR_SMEM);
        smem_set = 1;
    }

    k_gemm_pack<<<256 + 32, 256>>>(x, W, a, adj);
    k_aggr_v7<<<dim3(N_NODES / 64, HEADS, JSPLIT), 128, AGGR_SMEM>>>();
    k_combine<<<(N_NODES * F_OUT) / 256, 256>>>(out);
}

// round 16
// speedup vs baseline: 2.5654x; 2.5654x over previous
#include <cuda_runtime.h>
#include <math.h>
#include <stdint.h>

#define N_NODES 4096
#define F_IN    256
#define C_TOT   256
#define HEADS   4
#define F_OUT   64
#define JSPLIT  2
#define NWORDS  (N_NODES / 32)
#define JTILE   64
#define JPER    (N_NODES / JSPLIT)
#define NT      (JPER / JTILE)       // 32 tiles per CTA
#define HSTR    72
#define HS_FLOATS (JTILE * HSTR)     // 4608 floats per buffer
#define AGGR_SMEM (3 * HS_FLOATS * 4 + 3 * JTILE * 8)   // 56832 B
#define PACK_CTAS 1024

__device__ float    g_h [N_NODES * C_TOT];
__device__ float2   g_Pq[HEADS * N_NODES];   // (exp(e_i), exp(0.2 e_i)) [head][n]
__device__ float2   g_Qq[HEADS * N_NODES];   // (exp(e_j), exp(0.2 e_j)) [head][n]
__device__ unsigned g_adjm[N_NODES * NWORDS];
__device__ float    g_part[JSPLIT * HEADS * N_NODES * F_OUT];
__device__ float    g_pden[JSPLIT * HEADS * N_NODES];

// ---------------- cp.async helpers ----------------
__device__ __forceinline__ void cp16(uint32_t dst, const void* src) {
    asm volatile("cp.async.cg.shared.global [%0], [%1], 16;" :: "r"(dst), "l"(src));
}
#define CP_COMMIT() asm volatile("cp.async.commit_group;" ::: "memory")
#define CP_WAIT1()  asm volatile("cp.async.wait_group 1;" ::: "memory")
#define CP_WAIT0()  asm volatile("cp.async.wait_group 0;" ::: "memory")

// ---------------------------------------------------------------------------
// K1: fused gemm + exp epilogue (bid < 256) || adj bit-pack (bid >= 256).
//  1024 pack CTAs x 4 rows: full load parallelism (the R14 regression was
//  32 serial CTAs -> MLP 1). Pack DRAM stream overlaps gemm compute.
// ---------------------------------------------------------------------------
__global__ __launch_bounds__(256) void k_gemm_pack(const float* __restrict__ x,
                                                   const float* __restrict__ W,
                                                   const float* __restrict__ aa,
                                                   const int* __restrict__ adj) {
    const int bid = blockIdx.x;
    const int t   = threadIdx.x;

    if (bid >= 256) {
        // ---- pack: 1024 CTAs x 4 rows, 2 half-CTAs x 2 rows each ----
        const int pid  = bid - 256;
        const int half = t >> 7;
        const int tl   = t & 127;
        const int w    = tl >> 5;
        const int lane = tl & 31;
#pragma unroll
        for (int r = 0; r < 2; ++r) {
            const int row = pid * 4 + half * 2 + r;
            const size_t rb = (size_t)row * N_NODES;
#pragma unroll
            for (int c = w; c < 32; c += 4) {
                int4 v = *(const int4*)&adj[rb + c * 128 + lane * 4];
                unsigned n = (v.x != 0 ? 1u : 0u) | (v.y != 0 ? 2u : 0u)
                           | (v.z != 0 ? 4u : 0u) | (v.w != 0 ? 8u : 0u);
                unsigned word = n << (4 * (lane & 7));
                word |= __shfl_xor_sync(0xffffffffu, word, 1);
                word |= __shfl_xor_sync(0xffffffffu, word, 2);
                word |= __shfl_xor_sync(0xffffffffu, word, 4);
                if ((lane & 7) == 0)
                    g_adjm[row * NWORDS + c * 4 + (lane >> 3)] = word;
            }
        }
        return;
    }

    // ---- gemm: proven 64x64 tiling ----
    __shared__ __align__(16) float As[16][64];
    __shared__ __align__(16) float Bs[16][64];
    const int bx = bid & 3;            // head
    const int by = bid >> 2;
    const int n0 = bx * 64;
    const int m0 = by * 64;
    const int tx = t & 15, ty = t >> 4;

    float acc[4][4];
#pragma unroll
    for (int i = 0; i < 4; ++i)
#pragma unroll
        for (int j = 0; j < 4; ++j) acc[i][j] = 0.f;

    for (int k0 = 0; k0 < F_IN; k0 += 16) {
        {
            int row = t >> 2, k4 = (t & 3) * 4;
            float4 v = *(const float4*)&x[(m0 + row) * F_IN + k0 + k4];
            As[k4 + 0][row] = v.x; As[k4 + 1][row] = v.y;
            As[k4 + 2][row] = v.z; As[k4 + 3][row] = v.w;
        }
        {
            int krow = t >> 4, n4 = (t & 15) * 4;
            *(float4*)&Bs[krow][n4] = *(const float4*)&W[(k0 + krow) * C_TOT + n0 + n4];
        }
        __syncthreads();
#pragma unroll
        for (int kk = 0; kk < 16; ++kk) {
            float a[4], b[4];
            *(float4*)a = *(float4*)&As[kk][ty * 4];
            *(float4*)b = *(float4*)&Bs[kk][tx * 4];
#pragma unroll
            for (int i = 0; i < 4; ++i)
#pragma unroll
                for (int j = 0; j < 4; ++j) acc[i][j] += a[i] * b[j];
        }
        __syncthreads();
    }
#pragma unroll
    for (int i = 0; i < 4; ++i) {
        float4 v = make_float4(acc[i][0], acc[i][1], acc[i][2], acc[i][3]);
        *(float4*)&g_h[(size_t)(m0 + ty * 4 + i) * C_TOT + n0 + tx * 4] = v;
    }

    // fused exp-table epilogue
    const int f0 = tx * 4;
    float4 a1v = *(const float4*)&aa[f0];
    float4 a2v = *(const float4*)&aa[64 + f0];
#pragma unroll
    for (int i = 0; i < 4; ++i) {
        float ei = acc[i][0] * a1v.x + acc[i][1] * a1v.y
                 + acc[i][2] * a1v.z + acc[i][3] * a1v.w;
        float ej = acc[i][0] * a2v.x + acc[i][1] * a2v.y
                 + acc[i][2] * a2v.z + acc[i][3] * a2v.w;
#pragma unroll
        for (int off = 8; off; off >>= 1) {
            ei += __shfl_down_sync(0xffffffffu, ei, off, 16);
            ej += __shfl_down_sync(0xffffffffu, ej, off, 16);
        }
        if (tx == 0) {
            int idx = bx * N_NODES + m0 + ty * 4 + i;
            g_Pq[idx] = make_float2(expf(ei), expf(0.2f * ei));
            g_Qq[idx] = make_float2(expf(ej), expf(0.2f * ej));
        }
    }
}

// ---------------------------------------------------------------------------
// K3: tf32 mma.sync aggregation, v7: triple-buffered cp.async, one
//  __syncthreads per tile, JSPLIT=2 (512 CTAs, single wave).
// ---------------------------------------------------------------------------
__device__ __forceinline__ void mma_tf32(float c[4],
                                         unsigned a0, unsigned a1,
                                         unsigned a2, unsigned a3,
                                         unsigned b0, unsigned b1) {
    asm volatile(
        "mma.sync.aligned.m16n8k8.row.col.f32.tf32.tf32.f32 "
        "{%0,%1,%2,%3}, {%4,%5,%6,%7}, {%8,%9}, {%0,%1,%2,%3};"
        : "+f"(c[0]), "+f"(c[1]), "+f"(c[2]), "+f"(c[3])
        : "r"(a0), "r"(a1), "r"(a2), "r"(a3), "r"(b0), "r"(b1));
}
__device__ __forceinline__ unsigned to_tf32(float x) {
    unsigned u;
    asm("cvt.rna.tf32.f32 %0, %1;" : "=r"(u) : "f"(x));
    return u;
}

__global__ __launch_bounds__(128) void k_aggr_v7() {
    extern __shared__ __align__(16) float dsm[];
    float* hsb[3] = {dsm, dsm + HS_FLOATS, dsm + 2 * HS_FLOATS};
    float2* qsb[3] = {(float2*)(dsm + 3 * HS_FLOATS),
                      (float2*)(dsm + 3 * HS_FLOATS) + JTILE,
                      (float2*)(dsm + 3 * HS_FLOATS) + 2 * JTILE};

    const int t    = threadIdx.x;
    const int w    = t >> 5;
    const int lane = t & 31;
    const int g    = lane >> 2;
    const int tg   = lane & 3;
    const int head = blockIdx.y;
    const int js   = blockIdx.z;
    const int i0   = blockIdx.x * 64;
    const int row0 = i0 + w * 16 + g;
    const int row1 = row0 + 8;

    const float2 pa = g_Pq[head * N_NODES + row0];
    const float2 pb = g_Pq[head * N_NODES + row1];

    float acc[8][4];
#pragma unroll
    for (int nt = 0; nt < 8; ++nt)
#pragma unroll
        for (int k = 0; k < 4; ++k) acc[nt][k] = 0.f;
    float d0 = 0.f, d1 = 0.f;

    const unsigned* am0 = g_adjm + row0 * NWORDS;
    const unsigned* am1 = g_adjm + row1 * NWORDS;

    uint32_t hsa[3], qsa[3];
#pragma unroll
    for (int b = 0; b < 3; ++b) {
        hsa[b] = (uint32_t)__cvta_generic_to_shared(hsb[b]);
        qsa[b] = (uint32_t)__cvta_generic_to_shared(qsb[b]);
    }
    const int jbase = js * JPER;

    // ---- prologue: stage tiles 0,1 ----
#pragma unroll
    for (int pt = 0; pt < 2; ++pt) {
        const int j0 = jbase + pt * JTILE;
#pragma unroll
        for (int s = 0; s < 8; ++s) {
            int c = t + s * 128;
            int jj = c >> 4, cc = c & 15;
            cp16(hsa[pt] + (jj * HSTR + cc * 4) * 4,
                 &g_h[(size_t)(j0 + jj) * C_TOT + head * F_OUT + cc * 4]);
        }
        if (t < 32)
            cp16(qsa[pt] + t * 16, &g_Qq[head * N_NODES + j0 + t * 2]);
        CP_COMMIT();
    }

#pragma unroll 1
    for (int tile = 0; tile < NT; ++tile) {
        const int buf = tile % 3;
        const int j0  = jbase + tile * JTILE;

        if (tile < NT - 1) CP_WAIT1(); else CP_WAIT0();
        __syncthreads();

        const float*  hsp = hsb[buf];
        const float2* qsp = qsb[buf];
        const int wd = j0 >> 5;
        const unsigned m0a = am0[wd], m0b = am0[wd + 1];
        const unsigned m1a = am1[wd], m1b = am1[wd + 1];

#pragma unroll
        for (int kk = 0; kk < 8; ++kk) {
            const unsigned w0 = (kk < 4) ? m0a : m0b;
            const unsigned w1 = (kk < 4) ? m1a : m1b;
            const int sl   = (kk * 8) & 31;
            const int j_lo = kk * 8 + tg;
            const int j_hi = j_lo + 4;
            const float2 qlo = qsp[j_lo];
            const float2 qhi = qsp[j_hi];

            float v00 = fmaxf(pa.x * qlo.x, pa.y * qlo.y);
            float v10 = fmaxf(pb.x * qlo.x, pb.y * qlo.y);
            float v01 = fmaxf(pa.x * qhi.x, pa.y * qhi.y);
            float v11 = fmaxf(pb.x * qhi.x, pb.y * qhi.y);
            float a00 = ((w0 >> (sl + tg))     & 1u) ? v00 : 0.f;
            float a10 = ((w1 >> (sl + tg))     & 1u) ? v10 : 0.f;
            float a01 = ((w0 >> (sl + tg + 4)) & 1u) ? v01 : 0.f;
            float a11 = ((w1 >> (sl + tg + 4)) & 1u) ? v11 : 0.f;

            unsigned ua0 = to_tf32(a00);
            unsigned ua1 = to_tf32(a10);
            unsigned ua2 = to_tf32(a01);
            unsigned ua3 = to_tf32(a11);
            d0 += __uint_as_float(ua0) + __uint_as_float(ua2);
            d1 += __uint_as_float(ua1) + __uint_as_float(ua3);

            const float* blo = &hsp[j_lo * HSTR + g];
            const float* bhi = &hsp[j_hi * HSTR + g];
#pragma unroll
            for (int nt = 0; nt < 8; ++nt) {
                unsigned b0 = __float_as_uint(blo[nt * 8]);
                unsigned b1 = __float_as_uint(bhi[nt * 8]);
                mma_tf32(acc[nt], ua0, ua1, ua2, ua3, b0, b1);
            }
        }

        // ---- stage tile+2 into buf (tile+2)%3 ----
        if (tile + 2 < NT) {
            const int jn = j0 + 2 * JTILE;
            const int nb = (tile + 2) % 3;
#pragma unroll
            for (int s = 0; s < 8; ++s) {
                int c = t + s * 128;
                int jj = c >> 4, cc = c & 15;
                cp16(hsa[nb] + (jj * HSTR + cc * 4) * 4,
                     &g_h[(size_t)(jn + jj) * C_TOT + head * F_OUT + cc * 4]);
            }
            if (t < 32)
                cp16(qsa[nb] + t * 16, &g_Qq[head * N_NODES + jn + t * 2]);
            CP_COMMIT();
        }
    }

    // ---- epilogue ----
    d0 += __shfl_xor_sync(0xffffffffu, d0, 1);
    d0 += __shfl_xor_sync(0xffffffffu, d0, 2);
    d1 += __shfl_xor_sync(0xffffffffu, d1, 1);
    d1 += __shfl_xor_sync(0xffffffffu, d1, 2);

    const size_t pb2 = (size_t)(js * HEADS + head) * N_NODES;
    if (tg == 0) {
        g_pden[pb2 + row0] = d0;
        g_pden[pb2 + row1] = d1;
    }
    float* p0 = &g_part[(pb2 + row0) * F_OUT];
    float* p1 = &g_part[(pb2 + row1) * F_OUT];
#pragma unroll
    for (int nt = 0; nt < 8; ++nt) {
        const int f = nt * 8 + tg * 2;
        *(float2*)&p0[f] = make_float2(acc[nt][0], acc[nt][1]);
        *(float2*)&p1[f] = make_float2(acc[nt][2], acc[nt][3]);
    }
}

// ---------------------------------------------------------------------------
// K4: combine partials over j-splits and heads
// ---------------------------------------------------------------------------
__global__ __launch_bounds__(256) void k_combine(float* __restrict__ out) {
    const int t = blockIdx.x * 256 + threadIdx.x;
    const int i = t >> 6;
    const int f = t & 63;
    float v = 0.f;
#pragma unroll
    for (int h = 0; h < HEADS; ++h) {
        float num = 0.f, den = 0.f;
#pragma unroll
        for (int s = 0; s < JSPLIT; ++s) {
            num += g_part[((size_t)(s * HEADS + h) * N_NODES + i) * F_OUT + f];
            den += g_pden[(size_t)(s * HEADS + h) * N_NODES + i];
        }
        v += num / den;
    }
    out[t] = 0.25f * v;
}

// ---------------------------------------------------------------------------
extern "C" void kernel_launch(void* const* d_in, const int* in_sizes, int n_in,
                              void* d_out, int out_size) {
    const float* x   = (const float*)d_in[0];
    const int*   adj = (const int*)  d_in[1];
    const float* W   = (const float*)d_in[2];
    const float* a   = (const float*)d_in[3];
    float* out = (float*)d_out;

    static int smem_set = 0;
    if (!smem_set) {
        cudaFuncSetAttribute(k_aggr_v7,
                             cudaFuncAttributeMaxDynamicSharedMemorySize,
                             AGGR_SMEM);
        smem_set = 1;
    }

    k_gemm_pack<<<256 + PACK_CTAS, 256>>>(x, W, a, adj);
    k_aggr_v7<<<dim3(N_NODES / 64, HEADS, JSPLIT), 128, AGGR_SMEM>>>();
    k_combine<<<(N_NODES * F_OUT) / 256, 256>>>(out);
}